// round 16
// baseline (speedup 1.0000x reference)
#include <cuda_runtime.h>
#include <cuda_fp16.h>
#include <math.h>
#include <stdint.h>

#define DEV_INLINE __device__ __forceinline__

namespace cfg {
constexpr int N = 20000;
constexpr int E = 600000;
constexpr int D = 512;
constexpr int H = 8;
constexpr int HID = 1024;

// ---- fp32 scratch offsets ----
constexpr long OFF_CB   = 0;                          // E (csr-permuted att_bias)
constexpr long OFF_ATT  = OFF_CB  + (long)E;          // N*24 (att/den - pos)
constexpr long OFF_BQK  = OFF_ATT + (long)N * 24;     // 1024
constexpr long OFF_BIN  = OFF_BQK + 1024;             // 2048
constexpr long OFF_BEH  = OFF_BIN + 2048;             // 1024
constexpr long OFF_BFH  = OFF_BEH + 1024;             // 1024
constexpr long FTOTAL   = OFF_BFH + 1024;

// ---- int scratch ----
constexpr long I_ROWPTR = 0;            // N+1
constexpr long I_WOFS   = N + 1;        // N+1
constexpr long I_COL    = 2 * (N + 1);  // E
constexpr long ITOTAL   = I_COL + E;

// ---- fp16 scratch offsets ----
constexpr long B_ZATT = 0;
constexpr long B_ZMLP = B_ZATT + (long)N * D;
constexpr long B_QKA  = B_ZMLP + (long)N * D;     // [N,1024] q|k fp16
constexpr long B_H1E  = B_QKA  + (long)N * 1024;
constexpr long B_H1F  = B_H1E  + (long)N * HID;
constexpr long B_RAWF = B_H1F  + (long)N * HID;   // [N,1024] raw forces h1 (pre-gelu)
constexpr long B_H2E  = B_RAWF + (long)N * 1024;  // [N,1024] h2 energy fp16
constexpr long B_H2F  = B_H2E  + (long)N * 1024;  // [N,1024] h2 forces fp16
constexpr long B_WQK  = B_H2F  + (long)N * 1024;  // [1024, 512]
constexpr long B_WIN  = B_WQK  + 1024L * 512;     // [2048, 512]
constexpr long B_WEH  = B_WIN  + 2048L * 512;     // [1024, 1024]
constexpr long B_WFH  = B_WEH  + 1024L * 1024;
constexpr long BTOTAL = B_WFH  + 1024L * 1024;
}

__device__ float  g_f[cfg::FTOTAL];
__device__ int    g_i[cfg::ITOTAL];
__device__ __half g_hf[cfg::BTOTAL];

// ===========================================================================
// helpers
// ===========================================================================
DEV_INLINE float gelu_tanh(float x) {
    float x3 = x * x * x;
    float t = tanhf(0.7978845608028654f * (x + 0.044715f * x3));
    return 0.5f * x * (1.0f + t);
}
DEV_INLINE uint32_t smem_u32(const void* p) {
    uint32_t a;
    asm("{ .reg .u64 t; cvta.to.shared.u64 t, %1; cvt.u32.u64 %0, t; }" : "=r"(a) : "l"(p));
    return a;
}
DEV_INLINE void cp16(uint32_t dst, const void* src, int szbytes) {
    asm volatile("cp.async.cg.shared.global [%0], [%1], 16, %2;\n" :: "r"(dst), "l"(src), "r"(szbytes));
}
DEV_INLINE void cp_commit() { asm volatile("cp.async.commit_group;\n"); }
template <int NN>
DEV_INLINE void cp_wait() { asm volatile("cp.async.wait_group %0;\n" :: "n"(NN) : "memory"); }

DEV_INLINE void ldsm_x4(uint32_t& r0, uint32_t& r1, uint32_t& r2, uint32_t& r3, uint32_t addr) {
    asm volatile("ldmatrix.sync.aligned.m8n8.x4.shared.b16 {%0,%1,%2,%3}, [%4];"
                 : "=r"(r0), "=r"(r1), "=r"(r2), "=r"(r3) : "r"(addr));
}
DEV_INLINE void mma16816(float* c, const uint32_t* a, const uint32_t* b) {
    asm volatile("mma.sync.aligned.m16n8k16.row.col.f32.f16.f16.f32 "
                 "{%0,%1,%2,%3}, {%4,%5,%6,%7}, {%8,%9}, {%0,%1,%2,%3};"
                 : "+f"(c[0]), "+f"(c[1]), "+f"(c[2]), "+f"(c[3])
                 : "r"(a[0]), "r"(a[1]), "r"(a[2]), "r"(a[3]), "r"(b[0]), "r"(b[1]));
}
DEV_INLINE void h8_to_f(const float4& v, float* o) {
    const __half2* h2 = reinterpret_cast<const __half2*>(&v);
#pragma unroll
    for (int i = 0; i < 4; i++) {
        float2 f = __half22float2(h2[i]);
        o[2 * i] = f.x; o[2 * i + 1] = f.y;
    }
}

// ===========================================================================
// fp16 HMMA GEMM core (fp32 accumulate).
// tile 128x128, BK=64, 8 warps (4m x 2n), 3-stage cp.async pipeline,
// single barrier per chunk with early prefetch (race-free: the overwritten
// stage was last read in chunk c-1, protected by this chunk's barrier).
// ===========================================================================
constexpr int PADROW = 144;
constexpr int MAT_BYTES = 128 * PADROW;       // 18432
constexpr int STG_BYTES = 2 * MAT_BYTES;      // 36864
constexpr int GEMM_SMEM = 3 * STG_BYTES;      // 110592

struct GemmCore {
    uint32_t sb;
    int tid, lane, wm, wn, row0, col0;
    float acc[2][8][4];

    DEV_INLINE void init(const char* smem) {
        sb = smem_u32(smem);
        tid = threadIdx.x;
        int wid = tid >> 5;
        lane = tid & 31;
        wm = wid & 3;
        wn = wid >> 2;
        row0 = blockIdx.y * 128;
        col0 = blockIdx.x * 128;
    }

    DEV_INLINE void run(const __half* A, const __half* B, int M, int K) {
        const int nChunks = K >> 6;
        const int aRowOff = (lane & 7) + 8 * ((lane >> 3) & 1);
        const int aKbyte  = 16 * (lane >> 4);
        const int bRowOff = (lane & 7) + 8 * (lane >> 4);
        const int bKbyte  = 16 * ((lane >> 3) & 1);

#pragma unroll
        for (int mt = 0; mt < 2; mt++)
#pragma unroll
            for (int nt = 0; nt < 8; nt++)
#pragma unroll
                for (int q = 0; q < 4; q++) acc[mt][nt][q] = 0.f;

        auto load_stage = [&](int stage, int chunk) {
            const long k0 = (long)chunk << 6;
            const uint32_t base = sb + stage * STG_BYTES;
#pragma unroll
            for (int j = 0; j < 4; j++) {
                int i = tid + j * 256;        // 0..1023
                int r = i >> 3;               // 0..127
                int seg = i & 7;              // 0..7
                uint32_t so = r * PADROW + seg * 16;
                bool va = (row0 + r) < M;
                long ar = va ? (long)(row0 + r) : 0;
                cp16(base + so,             A + ar * K + k0 + seg * 8, va ? 16 : 0);
                long br = (long)(col0 + r);
                cp16(base + MAT_BYTES + so, B + br * K + k0 + seg * 8, 16);
            }
        };

        load_stage(0, 0);
        cp_commit();
        if (nChunks > 1) { load_stage(1, 1); cp_commit(); }

        for (int c = 0; c < nChunks; c++) {
            if (c + 1 < nChunks) cp_wait<1>(); else cp_wait<0>();
            __syncthreads();

            if (c + 2 < nChunks) {
                load_stage((c + 2) % 3, c + 2);
                cp_commit();
            }

            const uint32_t st = sb + (c % 3) * STG_BYTES;
#pragma unroll
            for (int kt = 0; kt < 4; kt++) {
                const int kb = kt * 32;
                uint32_t a[2][4];
#pragma unroll
                for (int mt = 0; mt < 2; mt++) {
                    uint32_t ro = (wm * 32 + mt * 16 + aRowOff) * PADROW + kb + aKbyte;
                    ldsm_x4(a[mt][0], a[mt][1], a[mt][2], a[mt][3], st + ro);
                }
                uint32_t b[8][2];
#pragma unroll
                for (int nt2 = 0; nt2 < 4; nt2++) {
                    uint32_t ro = (wn * 64 + nt2 * 16 + bRowOff) * PADROW + kb + bKbyte;
                    ldsm_x4(b[2 * nt2][0], b[2 * nt2][1], b[2 * nt2 + 1][0], b[2 * nt2 + 1][1],
                            st + MAT_BYTES + ro);
                }
#pragma unroll
                for (int mt = 0; mt < 2; mt++)
#pragma unroll
                    for (int nt = 0; nt < 8; nt++)
                        mma16816(acc[mt][nt], a[mt], b[nt]);
            }
        }
        __syncthreads();
    }
};

// epilogue iteration helper (variadic: body may contain commas)
#define EPI_LOOP(...)                                                         \
    {                                                                         \
        const int cRow = core.lane >> 2;                                      \
        const int cCol = 2 * (core.lane & 3);                                 \
        _Pragma("unroll")                                                     \
        for (int mt = 0; mt < 2; mt++) {                                      \
            _Pragma("unroll")                                                 \
            for (int half = 0; half < 2; half++) {                            \
                int r = core.row0 + core.wm * 32 + mt * 16 + cRow + half * 8; \
                if (r >= M) continue;                                         \
                _Pragma("unroll")                                             \
                for (int nt = 0; nt < 8; nt++) {                              \
                    int n = core.col0 + core.wn * 64 + nt * 8 + cCol;         \
                    float v0 = core.acc[mt][nt][half * 2 + 0];                \
                    float v1 = core.acc[mt][nt][half * 2 + 1];                \
                    __VA_ARGS__                                               \
                }                                                             \
            }                                                                 \
        }                                                                     \
    }

// ===========================================================================
// merged projection GEMM: blockIdx.x < 8 -> QK ; blockIdx.x >= 8 -> IN
// ===========================================================================
__global__ __launch_bounds__(256, 2) void gemm_proj(int M)
{
    extern __shared__ char smem[];
    GemmCore core; core.init(smem);
    const bool isQK = (blockIdx.x < 8);
    const int bx = isQK ? blockIdx.x : (blockIdx.x - 8);
    core.col0 = bx * 128;
    const long aOff = isQK ? cfg::B_ZATT : cfg::B_ZMLP;
    const long bOff = isQK ? cfg::B_WQK : cfg::B_WIN;
    const long biasOff = isQK ? cfg::OFF_BQK : cfg::OFF_BIN;
    core.run(g_hf + aOff, g_hf + bOff, M, 512);
    if (isQK) {
        EPI_LOOP(
            v0 += g_f[biasOff + n];
            v1 += g_f[biasOff + n + 1];
            __half2 hh; hh.x = __float2half(v0); hh.y = __float2half(v1);
            *reinterpret_cast<__half2*>(g_hf + cfg::B_QKA + (long)r * 1024 + n) = hh;
        )
    } else {
        EPI_LOOP(
            v0 += g_f[biasOff + n];
            v1 += g_f[biasOff + n + 1];
            if (n < 1024) {
                float gv0 = gelu_tanh(v0);
                float gv1 = gelu_tanh(v1);
                __half2 hh; hh.x = __float2half(gv0); hh.y = __float2half(gv1);
                *reinterpret_cast<__half2*>(g_hf + cfg::B_H1E + (long)r * 1024 + n) = hh;
            } else {
                __half2 hh; hh.x = __float2half(v0); hh.y = __float2half(v1);
                *reinterpret_cast<__half2*>(g_hf + cfg::B_RAWF + (long)r * 1024 + (n - 1024)) = hh;
            }
        )
    }
}

// merged hidden blocks: z=0 energy, z=1 forces. h2 fp16 = res(fp16,=A) + gelu(acc+bias)
__global__ __launch_bounds__(256, 2) void gemm_hidden(
    long aE, long aF, long bE, long bF, long biasE, long biasF, long cE, long cF, int M)
{
    extern __shared__ char smem[];
    GemmCore core; core.init(smem);
    const bool z = (blockIdx.z != 0);
    const long aOff = z ? aF : aE;
    const long bOff = z ? bF : bE;
    const long biasOff = z ? biasF : biasE;
    const long cOff = z ? cF : cE;
    core.run(g_hf + aOff, g_hf + bOff, M, 1024);
    EPI_LOOP(
        v0 = gelu_tanh(v0 + g_f[biasOff + n]);
        v1 = gelu_tanh(v1 + g_f[biasOff + n + 1]);
        long gidx = (long)r * 1024 + n;
        __half2 rh = *reinterpret_cast<const __half2*>(g_hf + aOff + gidx);
        v0 += __half2float(rh.x);
        v1 += __half2float(rh.y);
        __half2 oo; oo.x = __float2half(v0); oo.y = __float2half(v1);
        *reinterpret_cast<__half2*>(g_hf + cOff + gidx) = oo;
    )
}

// ===========================================================================
// weight conversion (transpose, fp16)
// ===========================================================================
__global__ void conv_all(const float* __restrict__ Wq, const float* __restrict__ Wk,
                         const float* __restrict__ Wei, const float* __restrict__ Wfi,
                         const float* __restrict__ Weh, const float* __restrict__ Wfh)
{
    long i = (long)blockIdx.x * blockDim.x + threadIdx.x;
    if (i >= 3670016L) return;
    const float* W; long o, dst; int NcS, Kd;
    if (i < 262144L)       { W = Wq;  o = i;            dst = cfg::B_WQK;          NcS = 512;  Kd = 512; }
    else if (i < 524288L)  { W = Wk;  o = i - 262144L;  dst = cfg::B_WQK + 262144; NcS = 512;  Kd = 512; }
    else if (i < 1048576L) { W = Wei; o = i - 524288L;  dst = cfg::B_WIN;          NcS = 1024; Kd = 512; }
    else if (i < 1572864L) { W = Wfi; o = i - 1048576L; dst = cfg::B_WIN + 524288; NcS = 1024; Kd = 512; }
    else if (i < 2621440L) { W = Weh; o = i - 1572864L; dst = cfg::B_WEH;          NcS = 1024; Kd = 1024; }
    else                   { W = Wfh; o = i - 2621440L; dst = cfg::B_WFH;          NcS = 1024; Kd = 1024; }
    int n = (int)(o / Kd);
    int k = (int)(o % Kd);
    g_hf[dst + o] = __float2half(W[(long)k * NcS + n]);
}

// biases + csr counter zeroing merged
__global__ void setup_kernel(const float* __restrict__ bq, const float* __restrict__ bk,
                             const float* __restrict__ bei, const float* __restrict__ bfi,
                             const float* __restrict__ beh, const float* __restrict__ bfh)
{
    int i = blockIdx.x * blockDim.x + threadIdx.x;
    if (i < 1024) g_f[cfg::OFF_BQK + i] = (i < 512) ? bq[i] : bk[i - 512];
    else if (i < 3072) { int j = i - 1024; g_f[cfg::OFF_BIN + j] = (j < 1024) ? bei[j] : bfi[j - 1024]; }
    else if (i < 4096) g_f[cfg::OFF_BEH + i - 3072] = beh[i - 3072];
    else if (i < 5120) g_f[cfg::OFF_BFH + i - 4096] = bfh[i - 4096];
    int z = i - 5120;
    if (z >= 0 && z <= cfg::N) g_i[cfg::I_WOFS + z] = 0;
}

// ===========================================================================
// CSR build (count vectorized: 4 edges per thread via int4)
// ===========================================================================
__global__ void csr_count(const int* __restrict__ ei) {
    int t = blockIdx.x * blockDim.x + threadIdx.x;
    int e0 = t * 4;
    if (e0 + 4 <= cfg::E) {
        int4 v = *reinterpret_cast<const int4*>(ei + e0);
        atomicAdd(&g_i[cfg::I_WOFS + v.x], 1);
        atomicAdd(&g_i[cfg::I_WOFS + v.y], 1);
        atomicAdd(&g_i[cfg::I_WOFS + v.z], 1);
        atomicAdd(&g_i[cfg::I_WOFS + v.w], 1);
    } else {
        for (int e = e0; e < cfg::E; e++)
            atomicAdd(&g_i[cfg::I_WOFS + ei[e]], 1);
    }
}
__global__ __launch_bounds__(1024) void csr_scan() {
    __shared__ int sh[1024];
    int t = threadIdx.x;
    int loc[20];
    int base = t * 20;
    int sum = 0;
#pragma unroll
    for (int j = 0; j < 20; j++) {
        int idx = base + j;
        int v = (idx < cfg::N) ? g_i[cfg::I_WOFS + idx] : 0;
        loc[j] = sum;
        sum += v;
    }
    sh[t] = sum;
    __syncthreads();
    for (int off = 1; off < 1024; off <<= 1) {
        int v = (t >= off) ? sh[t - off] : 0;
        __syncthreads();
        sh[t] += v;
        __syncthreads();
    }
    int pre = (t == 0) ? 0 : sh[t - 1];
#pragma unroll
    for (int j = 0; j < 20; j++) {
        int idx = base + j;
        if (idx < cfg::N) {
            g_i[cfg::I_ROWPTR + idx] = pre + loc[j];
            g_i[cfg::I_WOFS + idx]   = pre + loc[j];
        }
    }
    if (t == 0) g_i[cfg::I_ROWPTR + cfg::N] = cfg::E;
}
__global__ void csr_scatter(const int* __restrict__ ei, const float* __restrict__ att_bias) {
    int e = blockIdx.x * blockDim.x + threadIdx.x;
    if (e >= cfg::E) return;
    int r = ei[e];
    int p = atomicAdd(&g_i[cfg::I_WOFS + r], 1);
    g_i[cfg::I_COL + p] = ei[cfg::E + e];
    g_f[cfg::OFF_CB + p] = att_bias[e];
}

// ===========================================================================
// one-pass edge attention (fp16 q/k): warp per node. NO online max:
// logits ~ N(0,1) by construction (LN'd activations x 0.02-scale weights,
// bias ~ N(0,1)); |logit| < ~8 over 600K draws, exp safe to 88. Dropping the
// max removes the serial rescale chain -> independent FMA accumulators.
// Normalized ratio a/d is mathematically identical to the max-subtracted form.
// ===========================================================================
__global__ __launch_bounds__(256) void edge_attn_kernel(const float* __restrict__ pos) {
    int n = blockIdx.x * 8 + (threadIdx.x >> 5);
    if (n >= cfg::N) return;
    int lane = threadIdx.x & 31;

    int base = g_i[cfg::I_ROWPTR + n];
    int deg  = g_i[cfg::I_ROWPTR + n + 1] - base;

    const float4* qr = reinterpret_cast<const float4*>(g_hf + cfg::B_QKA + (long)n * 1024) + lane * 2;
    float q[16];
    h8_to_f(qr[0], q);
    h8_to_f(qr[1], q + 8);

    float prv = (lane < 3) ? pos[(long)n * 3 + lane] : 0.f;
    float prx = __shfl_sync(0xffffffffu, prv, 0);
    float pry = __shfl_sync(0xffffffffu, prv, 1);
    float prz = __shfl_sync(0xffffffffu, prv, 2);

    float d = 0.f, a0 = 0.f, a1 = 0.f, a2 = 0.f;

    int i = 0;
    int c0 = 0, c1 = 0;
    float b0 = 0.f, b1 = 0.f;
    if (i + 2 <= deg) {
        c0 = g_i[cfg::I_COL + base];
        c1 = g_i[cfg::I_COL + base + 1];
        b0 = g_f[cfg::OFF_CB + base];
        b1 = g_f[cfg::OFF_CB + base + 1];
    }
    for (; i + 2 <= deg; i += 2) {
        const float4* kr0 = reinterpret_cast<const float4*>(g_hf + cfg::B_QKA + (long)c0 * 1024 + 512) + lane * 2;
        const float4* kr1 = reinterpret_cast<const float4*>(g_hf + cfg::B_QKA + (long)c1 * 1024 + 512) + lane * 2;
        float4 v00 = kr0[0], v01 = kr0[1];
        float4 v10 = kr1[0], v11 = kr1[1];
        float pv0 = (lane < 3) ? pos[(long)c0 * 3 + lane] : 0.f;
        float pv1 = (lane < 3) ? pos[(long)c1 * 3 + lane] : 0.f;
        float lb0 = b0, lb1 = b1;
        if (i + 4 <= deg) {
            c0 = g_i[cfg::I_COL + base + i + 2];
            c1 = g_i[cfg::I_COL + base + i + 3];
            b0 = g_f[cfg::OFF_CB + base + i + 2];
            b1 = g_f[cfg::OFF_CB + base + i + 3];
        }
        float kv[16];
        float s0 = 0.f, s1 = 0.f;
        h8_to_f(v00, kv); h8_to_f(v01, kv + 8);
#pragma unroll
        for (int j = 0; j < 16; j++) s0 = fmaf(q[j], kv[j], s0);
        h8_to_f(v10, kv); h8_to_f(v11, kv + 8);
#pragma unroll
        for (int j = 0; j < 16; j++) s1 = fmaf(q[j], kv[j], s1);
        s0 += __shfl_xor_sync(0xffffffffu, s0, 1);
        s1 += __shfl_xor_sync(0xffffffffu, s1, 1);
        s0 += __shfl_xor_sync(0xffffffffu, s0, 2);
        s1 += __shfl_xor_sync(0xffffffffu, s1, 2);

        float p0x = __shfl_sync(0xffffffffu, pv0, 0);
        float p0y = __shfl_sync(0xffffffffu, pv0, 1);
        float p0z = __shfl_sync(0xffffffffu, pv0, 2);
        float p1x = __shfl_sync(0xffffffffu, pv1, 0);
        float p1y = __shfl_sync(0xffffffffu, pv1, 1);
        float p1z = __shfl_sync(0xffffffffu, pv1, 2);

        float p0 = expf(fmaf(s0, 0.125f, lb0));
        float p1 = expf(fmaf(s1, 0.125f, lb1));
        d  += p0 + p1;
        a0 = fmaf(p0, p0x, fmaf(p1, p1x, a0));
        a1 = fmaf(p0, p0y, fmaf(p1, p1y, a1));
        a2 = fmaf(p0, p0z, fmaf(p1, p1z, a2));
    }
    for (; i < deg; i++) {
        int c = g_i[cfg::I_COL + base + i];
        float bias = g_f[cfg::OFF_CB + base + i];
        const float4* kr = reinterpret_cast<const float4*>(g_hf + cfg::B_QKA + (long)c * 1024 + 512) + lane * 2;
        float kv[16];
        h8_to_f(kr[0], kv);
        h8_to_f(kr[1], kv + 8);
        float s = 0.f;
#pragma unroll
        for (int j = 0; j < 16; j++) s = fmaf(q[j], kv[j], s);
        s += __shfl_xor_sync(0xffffffffu, s, 1);
        s += __shfl_xor_sync(0xffffffffu, s, 2);

        float pv = (lane < 3) ? pos[(long)c * 3 + lane] : 0.f;
        float px = __shfl_sync(0xffffffffu, pv, 0);
        float py = __shfl_sync(0xffffffffu, pv, 1);
        float pz = __shfl_sync(0xffffffffu, pv, 2);

        float p = expf(fmaf(s, 0.125f, bias));
        d  += p;
        a0 = fmaf(p, px, a0);
        a1 = fmaf(p, py, a1);
        a2 = fmaf(p, pz, a2);
    }

    if ((lane & 3) == 0) {
        int h = lane >> 2;
        float inv = (d > 0.f) ? 1.0f / d : 0.f;
        long o = (long)n * 24 + h * 3;
        g_f[cfg::OFF_ATT + o + 0] = a0 * inv - prx;
        g_f[cfg::OFF_ATT + o + 1] = a1 * inv - pry;
        g_f[cfg::OFF_ATT + o + 2] = a2 * inv - prz;
    }
}

// ===========================================================================
// forces h1 fixup: h1f = gelu(raw(fp16) + attminus @ W24) -> fp16 (2-row ILP)
// ===========================================================================
constexpr int FIX_SMEM = (24 * 1025 + 16 * 24) * 4;

__global__ __launch_bounds__(256) void forces_h1_kernel(const float* __restrict__ Wfi) {
    extern __shared__ float sw[];
    float* w24 = sw;
    float* am  = sw + 24 * 1025;
    int n0 = blockIdx.x * 16;
    int t = threadIdx.x;

    for (int idx = t; idx < 24 * 1024; idx += 256) {
        int k = idx >> 10, j = idx & 1023;
        w24[k * 1025 + j] = Wfi[(long)(512 + k) * 1024 + j];
    }
    for (int idx = t; idx < 16 * 24; idx += 256) {
        int i = idx / 24, k = idx % 24;
        am[idx] = g_f[cfg::OFF_ATT + (long)(n0 + i) * 24 + k];
    }
    __syncthreads();

#pragma unroll
    for (int jj = 0; jj < 4; jj++) {
        int j = t + jj * 256;
        float w[24];
#pragma unroll
        for (int k = 0; k < 24; k++) w[k] = w24[k * 1025 + j];
#pragma unroll 2
        for (int i = 0; i < 16; i += 2) {
            long gi0 = (long)(n0 + i) * 1024 + j;
            long gi1 = (long)(n0 + i + 1) * 1024 + j;
            float v0 = __half2float(g_hf[cfg::B_RAWF + gi0]);
            float v1 = __half2float(g_hf[cfg::B_RAWF + gi1]);
#pragma unroll
            for (int k = 0; k < 24; k++) {
                v0 = fmaf(am[i * 24 + k], w[k], v0);
                v1 = fmaf(am[(i + 1) * 24 + k], w[k], v1);
            }
            g_hf[cfg::B_H1F + gi0] = __float2half(gelu_tanh(v0));
            g_hf[cfg::B_H1F + gi1] = __float2half(gelu_tanh(v1));
        }
    }
}

// ===========================================================================
// double LayerNorm -> fp16 activations
// ===========================================================================
__global__ __launch_bounds__(128) void ln_kernel(
    const float* __restrict__ x,
    const float* __restrict__ ga, const float* __restrict__ ba,
    const float* __restrict__ gm, const float* __restrict__ bm)
{
    int row = blockIdx.x;
    int t = threadIdx.x;
    const float* xr = x + (long)row * cfg::D;

    float v[4];
    float s = 0.f, ss = 0.f;
#pragma unroll
    for (int i = 0; i < 4; i++) {
        v[i] = xr[t + 128 * i];
        s += v[i];
        ss += v[i] * v[i];
    }
    __shared__ float sh[2][4];
#pragma unroll
    for (int o = 16; o > 0; o >>= 1) {
        s  += __shfl_down_sync(0xffffffffu, s, o);
        ss += __shfl_down_sync(0xffffffffu, ss, o);
    }
    if ((t & 31) == 0) { sh[0][t >> 5] = s; sh[1][t >> 5] = ss; }
    __syncthreads();
    if (t == 0) {
        float S  = sh[0][0] + sh[0][1] + sh[0][2] + sh[0][3];
        float SS = sh[1][0] + sh[1][1] + sh[1][2] + sh[1][3];
        float mean = S / cfg::D;
        float var  = SS / cfg::D - mean * mean;
        sh[0][0] = mean;
        sh[1][0] = rsqrtf(var + 1e-5f);
    }
    __syncthreads();
    float mean = sh[0][0], rstd = sh[1][0];
#pragma unroll
    for (int i = 0; i < 4; i++) {
        int c = t + 128 * i;
        float zn = (v[i] - mean) * rstd;
        g_hf[cfg::B_ZATT + (long)row * cfg::D + c] = __float2half(zn * ga[c] + ba[c]);
        g_hf[cfg::B_ZMLP + (long)row * cfg::D + c] = __float2half(zn * gm[c] + bm[c]);
    }
}

// ===========================================================================
// fused output heads (h2 fp16), 2 nodes per block (128 threads each)
// ===========================================================================
__global__ __launch_bounds__(256) void heads_kernel(
    const float* __restrict__ Weo, const float* __restrict__ beo,
    const float* __restrict__ Wfo, const float* __restrict__ bfo,
    float* __restrict__ out)
{
    int sub = threadIdx.x >> 7;           // 0 or 1
    int n = blockIdx.x * 2 + sub;
    int t = threadIdx.x & 127;
    const __half2* he = reinterpret_cast<const __half2*>(g_hf + cfg::B_H2E + (long)n * 1024);
    const __half2* hf = reinterpret_cast<const __half2*>(g_hf + cfg::B_H2F + (long)n * 1024);
    float s = 0.f, s0 = 0.f, s1 = 0.f, s2 = 0.f;
#pragma unroll
    for (int jj = 0; jj < 4; jj++) {
        int j = t + jj * 128;
        float2 e2 = __half22float2(he[j]);
        float2 f2 = __half22float2(hf[j]);
        int j0 = 2 * j, j1 = 2 * j + 1;
        s += e2.x * Weo[j0] + e2.y * Weo[j1];
        s0 += f2.x * Wfo[j0 * 3 + 0] + f2.y * Wfo[j1 * 3 + 0];
        s1 += f2.x * Wfo[j0 * 3 + 1] + f2.y * Wfo[j1 * 3 + 1];
        s2 += f2.x * Wfo[j0 * 3 + 2] + f2.y * Wfo[j1 * 3 + 2];
    }
    __shared__ float sh[2][4][4];
#pragma unroll
    for (int o = 16; o > 0; o >>= 1) {
        s  += __shfl_down_sync(0xffffffffu, s,  o);
        s0 += __shfl_down_sync(0xffffffffu, s0, o);
        s1 += __shfl_down_sync(0xffffffffu, s1, o);
        s2 += __shfl_down_sync(0xffffffffu, s2, o);
    }
    if ((t & 31) == 0) {
        int w = t >> 5;   // 0..3
        sh[sub][0][w] = s; sh[sub][1][w] = s0; sh[sub][2][w] = s1; sh[sub][3][w] = s2;
    }
    __syncthreads();
    if (t == 0) {
        float t0 = 0.f, t1 = 0.f, t2 = 0.f, t3 = 0.f;
#pragma unroll
        for (int i = 0; i < 4; i++) { t0 += sh[sub][0][i]; t1 += sh[sub][1][i]; t2 += sh[sub][2][i]; t3 += sh[sub][3][i]; }
        out[n] = t0 + beo[0];
        out[(long)cfg::N + (long)n * 3 + 0] = t1 + bfo[0];
        out[(long)cfg::N + (long)n * 3 + 1] = t2 + bfo[1];
        out[(long)cfg::N + (long)n * 3 + 2] = t3 + bfo[2];
    }
}

// ===========================================================================
extern "C" void kernel_launch(void* const* d_in, const int* in_sizes, int n_in,
                              void* d_out, int out_size)
{
    const float* x        = (const float*)d_in[0];
    const int*   ei       = (const int*)  d_in[1];
    const float* att_bias = (const float*)d_in[2];
    const float* pos      = (const float*)d_in[3];
    const float* g_att  = (const float*)d_in[5];
    const float* b_att  = (const float*)d_in[6];
    const float* g_mlp  = (const float*)d_in[7];
    const float* b_mlp  = (const float*)d_in[8];
    const float* Wq     = (const float*)d_in[9];
    const float* bq     = (const float*)d_in[10];
    const float* Wk     = (const float*)d_in[11];
    const float* bk     = (const float*)d_in[12];
    const float* We_in  = (const float*)d_in[13];
    const float* be_in  = (const float*)d_in[14];
    const float* We_h   = (const float*)d_in[15];
    const float* be_h   = (const float*)d_in[16];
    const float* We_out = (const float*)d_in[17];
    const float* be_out = (const float*)d_in[18];
    const float* Wf_in  = (const float*)d_in[19];
    const float* bf_in  = (const float*)d_in[20];
    const float* Wf_h   = (const float*)d_in[21];
    const float* bf_h   = (const float*)d_in[22];
    const float* Wf_out = (const float*)d_in[23];
    const float* bf_out = (const float*)d_in[24];
    float* out = (float*)d_out;

    cudaFuncSetAttribute(gemm_proj,   cudaFuncAttributeMaxDynamicSharedMemorySize, GEMM_SMEM);
    cudaFuncSetAttribute(gemm_hidden, cudaFuncAttributeMaxDynamicSharedMemorySize, GEMM_SMEM);
    cudaFuncSetAttribute(forces_h1_kernel, cudaFuncAttributeMaxDynamicSharedMemorySize, FIX_SMEM);

    const int MB = (cfg::N + 127) / 128;   // 157

    // 0: biases + zero csr counters
    setup_kernel<<<(5120 + cfg::N + 1 + 255) / 256, 256>>>(bq, bk, be_in, bf_in, be_h, bf_h);
    // 1: LayerNorm
    ln_kernel<<<cfg::N, 128>>>(x, g_att, b_att, g_mlp, b_mlp);
    // 2: weights
    conv_all<<<(unsigned)((3670016L + 255) / 256), 256>>>(Wq, Wk, We_in, Wf_in, We_h, Wf_h);
    // 3: csr count (int4-vectorized)
    csr_count<<<(cfg::E / 4 + 255) / 256, 256>>>(ei);
    // 4: merged QK + in-projection (x<8: QK, x>=8: IN)
    gemm_proj<<<dim3(24, MB), 256, GEMM_SMEM>>>(cfg::N);
    // 5: csr scan
    csr_scan<<<1, 1024>>>();
    // 6: csr scatter
    csr_scatter<<<(cfg::E + 255) / 256, 256>>>(ei, att_bias);
    // 7: one-pass edge attention (no-max softmax, 2-way ILP, prefetch)
    edge_attn_kernel<<<(cfg::N + 7) / 8, 256>>>(pos);
    // 8: forces h1 fixup
    forces_h1_kernel<<<cfg::N / 16, 256, FIX_SMEM>>>(Wf_in);
    // 9: merged hidden blocks (z: 0=energy, 1=forces), h2 -> fp16
    gemm_hidden<<<dim3(8, MB, 2), 256, GEMM_SMEM>>>(
        cfg::B_H1E, cfg::B_H1F, cfg::B_WEH, cfg::B_WFH,
        cfg::OFF_BEH, cfg::OFF_BFH, cfg::B_H2E, cfg::B_H2F, cfg::N);
    // 10: output heads (2 nodes/block)
    heads_kernel<<<cfg::N / 2, 256>>>(We_out, be_out, Wf_out, bf_out, out);
}

// round 17
// speedup vs baseline: 1.4799x; 1.4799x over previous
#include <cuda_runtime.h>
#include <cuda_fp16.h>
#include <math.h>
#include <stdint.h>

#define DEV_INLINE __device__ __forceinline__

namespace cfg {
constexpr int N = 20000;
constexpr int E = 600000;
constexpr int D = 512;
constexpr int H = 8;
constexpr int HID = 1024;

// ---- fp32 scratch offsets ----
constexpr long OFF_CB   = 0;                          // E (csr-permuted att_bias)
constexpr long OFF_ATT  = OFF_CB  + (long)E;          // N*24 (att/den - pos)
constexpr long OFF_BQK  = OFF_ATT + (long)N * 24;     // 1024
constexpr long OFF_BIN  = OFF_BQK + 1024;             // 2048
constexpr long OFF_BEH  = OFF_BIN + 2048;             // 1024
constexpr long OFF_BFH  = OFF_BEH + 1024;             // 1024
constexpr long FTOTAL   = OFF_BFH + 1024;

// ---- int scratch ----
constexpr long I_ROWPTR = 0;            // N+1
constexpr long I_WOFS   = N + 1;        // N+1
constexpr long I_COL    = 2 * (N + 1);  // E
constexpr long ITOTAL   = I_COL + E;

// ---- fp16 scratch offsets ----
constexpr long B_ZATT = 0;
constexpr long B_ZMLP = B_ZATT + (long)N * D;
constexpr long B_QKA  = B_ZMLP + (long)N * D;     // [N,1024] q|k fp16
constexpr long B_H1E  = B_QKA  + (long)N * 1024;
constexpr long B_H1F  = B_H1E  + (long)N * HID;
constexpr long B_RAWF = B_H1F  + (long)N * HID;   // [N,1024] raw forces h1 (pre-gelu)
constexpr long B_H2E  = B_RAWF + (long)N * 1024;  // [N,1024] h2 energy fp16
constexpr long B_H2F  = B_H2E  + (long)N * 1024;  // [N,1024] h2 forces fp16
constexpr long B_WQK  = B_H2F  + (long)N * 1024;  // [1024, 512]
constexpr long B_WIN  = B_WQK  + 1024L * 512;     // [2048, 512]
constexpr long B_WEH  = B_WIN  + 2048L * 512;     // [1024, 1024]
constexpr long B_WFH  = B_WEH  + 1024L * 1024;
constexpr long BTOTAL = B_WFH  + 1024L * 1024;
}

__device__ float  g_f[cfg::FTOTAL];
__device__ int    g_i[cfg::ITOTAL];
__device__ __half g_hf[cfg::BTOTAL];

// ===========================================================================
// helpers
// ===========================================================================
DEV_INLINE float gelu_tanh(float x) {
    float x3 = x * x * x;
    float t = tanhf(0.7978845608028654f * (x + 0.044715f * x3));
    return 0.5f * x * (1.0f + t);
}
DEV_INLINE uint32_t smem_u32(const void* p) {
    uint32_t a;
    asm("{ .reg .u64 t; cvta.to.shared.u64 t, %1; cvt.u32.u64 %0, t; }" : "=r"(a) : "l"(p));
    return a;
}
DEV_INLINE void cp16(uint32_t dst, const void* src, int szbytes) {
    asm volatile("cp.async.cg.shared.global [%0], [%1], 16, %2;\n" :: "r"(dst), "l"(src), "r"(szbytes));
}
DEV_INLINE void cp_commit() { asm volatile("cp.async.commit_group;\n"); }
template <int NN>
DEV_INLINE void cp_wait() { asm volatile("cp.async.wait_group %0;\n" :: "n"(NN) : "memory"); }

DEV_INLINE void ldsm_x4(uint32_t& r0, uint32_t& r1, uint32_t& r2, uint32_t& r3, uint32_t addr) {
    asm volatile("ldmatrix.sync.aligned.m8n8.x4.shared.b16 {%0,%1,%2,%3}, [%4];"
                 : "=r"(r0), "=r"(r1), "=r"(r2), "=r"(r3) : "r"(addr));
}
DEV_INLINE void mma16816(float* c, const uint32_t* a, const uint32_t* b) {
    asm volatile("mma.sync.aligned.m16n8k16.row.col.f32.f16.f16.f32 "
                 "{%0,%1,%2,%3}, {%4,%5,%6,%7}, {%8,%9}, {%0,%1,%2,%3};"
                 : "+f"(c[0]), "+f"(c[1]), "+f"(c[2]), "+f"(c[3])
                 : "r"(a[0]), "r"(a[1]), "r"(a[2]), "r"(a[3]), "r"(b[0]), "r"(b[1]));
}
DEV_INLINE void h8_to_f(const float4& v, float* o) {
    const __half2* h2 = reinterpret_cast<const __half2*>(&v);
#pragma unroll
    for (int i = 0; i < 4; i++) {
        float2 f = __half22float2(h2[i]);
        o[2 * i] = f.x; o[2 * i + 1] = f.y;
    }
}

// ===========================================================================
// fp16 HMMA GEMM core (fp32 accumulate).
// tile 128x128, BK=64, 8 warps (4m x 2n), 3-stage cp.async pipeline,
// single barrier per chunk with early prefetch (race-free: the overwritten
// stage was last read in chunk c-1, protected by this chunk's barrier).
// ===========================================================================
constexpr int PADROW = 144;
constexpr int MAT_BYTES = 128 * PADROW;       // 18432
constexpr int STG_BYTES = 2 * MAT_BYTES;      // 36864
constexpr int GEMM_SMEM = 3 * STG_BYTES;      // 110592

struct GemmCore {
    uint32_t sb;
    int tid, lane, wm, wn, row0, col0;
    float acc[2][8][4];

    DEV_INLINE void init(const char* smem) {
        sb = smem_u32(smem);
        tid = threadIdx.x;
        int wid = tid >> 5;
        lane = tid & 31;
        wm = wid & 3;
        wn = wid >> 2;
        row0 = blockIdx.y * 128;
        col0 = blockIdx.x * 128;
    }

    DEV_INLINE void run(const __half* A, const __half* B, int M, int K) {
        const int nChunks = K >> 6;
        const int aRowOff = (lane & 7) + 8 * ((lane >> 3) & 1);
        const int aKbyte  = 16 * (lane >> 4);
        const int bRowOff = (lane & 7) + 8 * (lane >> 4);
        const int bKbyte  = 16 * ((lane >> 3) & 1);

#pragma unroll
        for (int mt = 0; mt < 2; mt++)
#pragma unroll
            for (int nt = 0; nt < 8; nt++)
#pragma unroll
                for (int q = 0; q < 4; q++) acc[mt][nt][q] = 0.f;

        auto load_stage = [&](int stage, int chunk) {
            const long k0 = (long)chunk << 6;
            const uint32_t base = sb + stage * STG_BYTES;
#pragma unroll
            for (int j = 0; j < 4; j++) {
                int i = tid + j * 256;        // 0..1023
                int r = i >> 3;               // 0..127
                int seg = i & 7;              // 0..7
                uint32_t so = r * PADROW + seg * 16;
                bool va = (row0 + r) < M;
                long ar = va ? (long)(row0 + r) : 0;
                cp16(base + so,             A + ar * K + k0 + seg * 8, va ? 16 : 0);
                long br = (long)(col0 + r);
                cp16(base + MAT_BYTES + so, B + br * K + k0 + seg * 8, 16);
            }
        };

        load_stage(0, 0);
        cp_commit();
        if (nChunks > 1) { load_stage(1, 1); cp_commit(); }

        for (int c = 0; c < nChunks; c++) {
            if (c + 1 < nChunks) cp_wait<1>(); else cp_wait<0>();
            __syncthreads();

            if (c + 2 < nChunks) {
                load_stage((c + 2) % 3, c + 2);
                cp_commit();
            }

            const uint32_t st = sb + (c % 3) * STG_BYTES;
#pragma unroll
            for (int kt = 0; kt < 4; kt++) {
                const int kb = kt * 32;
                uint32_t a[2][4];
#pragma unroll
                for (int mt = 0; mt < 2; mt++) {
                    uint32_t ro = (wm * 32 + mt * 16 + aRowOff) * PADROW + kb + aKbyte;
                    ldsm_x4(a[mt][0], a[mt][1], a[mt][2], a[mt][3], st + ro);
                }
                uint32_t b[8][2];
#pragma unroll
                for (int nt2 = 0; nt2 < 4; nt2++) {
                    uint32_t ro = (wn * 64 + nt2 * 16 + bRowOff) * PADROW + kb + bKbyte;
                    ldsm_x4(b[2 * nt2][0], b[2 * nt2][1], b[2 * nt2 + 1][0], b[2 * nt2 + 1][1],
                            st + MAT_BYTES + ro);
                }
#pragma unroll
                for (int mt = 0; mt < 2; mt++)
#pragma unroll
                    for (int nt = 0; nt < 8; nt++)
                        mma16816(acc[mt][nt], a[mt], b[nt]);
            }
        }
        __syncthreads();
    }
};

// epilogue iteration helper (variadic: body may contain commas)
#define EPI_LOOP(...)                                                         \
    {                                                                         \
        const int cRow = core.lane >> 2;                                      \
        const int cCol = 2 * (core.lane & 3);                                 \
        _Pragma("unroll")                                                     \
        for (int mt = 0; mt < 2; mt++) {                                      \
            _Pragma("unroll")                                                 \
            for (int half = 0; half < 2; half++) {                            \
                int r = core.row0 + core.wm * 32 + mt * 16 + cRow + half * 8; \
                if (r >= M) continue;                                         \
                _Pragma("unroll")                                             \
                for (int nt = 0; nt < 8; nt++) {                              \
                    int n = core.col0 + core.wn * 64 + nt * 8 + cCol;         \
                    float v0 = core.acc[mt][nt][half * 2 + 0];                \
                    float v1 = core.acc[mt][nt][half * 2 + 1];                \
                    __VA_ARGS__                                               \
                }                                                             \
            }                                                                 \
        }                                                                     \
    }

// ===========================================================================
// merged projection GEMM: blockIdx.x < 8 -> QK ; blockIdx.x >= 8 -> IN
// ===========================================================================
__global__ __launch_bounds__(256, 2) void gemm_proj(int M)
{
    extern __shared__ char smem[];
    GemmCore core; core.init(smem);
    const bool isQK = (blockIdx.x < 8);
    const int bx = isQK ? blockIdx.x : (blockIdx.x - 8);
    core.col0 = bx * 128;
    const long aOff = isQK ? cfg::B_ZATT : cfg::B_ZMLP;
    const long bOff = isQK ? cfg::B_WQK : cfg::B_WIN;
    const long biasOff = isQK ? cfg::OFF_BQK : cfg::OFF_BIN;
    core.run(g_hf + aOff, g_hf + bOff, M, 512);
    if (isQK) {
        EPI_LOOP(
            v0 += g_f[biasOff + n];
            v1 += g_f[biasOff + n + 1];
            __half2 hh; hh.x = __float2half(v0); hh.y = __float2half(v1);
            *reinterpret_cast<__half2*>(g_hf + cfg::B_QKA + (long)r * 1024 + n) = hh;
        )
    } else {
        EPI_LOOP(
            v0 += g_f[biasOff + n];
            v1 += g_f[biasOff + n + 1];
            if (n < 1024) {
                float gv0 = gelu_tanh(v0);
                float gv1 = gelu_tanh(v1);
                __half2 hh; hh.x = __float2half(gv0); hh.y = __float2half(gv1);
                *reinterpret_cast<__half2*>(g_hf + cfg::B_H1E + (long)r * 1024 + n) = hh;
            } else {
                __half2 hh; hh.x = __float2half(v0); hh.y = __float2half(v1);
                *reinterpret_cast<__half2*>(g_hf + cfg::B_RAWF + (long)r * 1024 + (n - 1024)) = hh;
            }
        )
    }
}

// merged hidden blocks: z=0 energy, z=1 forces. h2 fp16 = res(fp16,=A) + gelu(acc+bias)
__global__ __launch_bounds__(256, 2) void gemm_hidden(
    long aE, long aF, long bE, long bF, long biasE, long biasF, long cE, long cF, int M)
{
    extern __shared__ char smem[];
    GemmCore core; core.init(smem);
    const bool z = (blockIdx.z != 0);
    const long aOff = z ? aF : aE;
    const long bOff = z ? bF : bE;
    const long biasOff = z ? biasF : biasE;
    const long cOff = z ? cF : cE;
    core.run(g_hf + aOff, g_hf + bOff, M, 1024);
    EPI_LOOP(
        v0 = gelu_tanh(v0 + g_f[biasOff + n]);
        v1 = gelu_tanh(v1 + g_f[biasOff + n + 1]);
        long gidx = (long)r * 1024 + n;
        __half2 rh = *reinterpret_cast<const __half2*>(g_hf + aOff + gidx);
        v0 += __half2float(rh.x);
        v1 += __half2float(rh.y);
        __half2 oo; oo.x = __float2half(v0); oo.y = __float2half(v1);
        *reinterpret_cast<__half2*>(g_hf + cOff + gidx) = oo;
    )
}

// ===========================================================================
// weight conversion (transpose, fp16)
// ===========================================================================
__global__ void conv_all(const float* __restrict__ Wq, const float* __restrict__ Wk,
                         const float* __restrict__ Wei, const float* __restrict__ Wfi,
                         const float* __restrict__ Weh, const float* __restrict__ Wfh)
{
    long i = (long)blockIdx.x * blockDim.x + threadIdx.x;
    if (i >= 3670016L) return;
    const float* W; long o, dst; int NcS, Kd;
    if (i < 262144L)       { W = Wq;  o = i;            dst = cfg::B_WQK;          NcS = 512;  Kd = 512; }
    else if (i < 524288L)  { W = Wk;  o = i - 262144L;  dst = cfg::B_WQK + 262144; NcS = 512;  Kd = 512; }
    else if (i < 1048576L) { W = Wei; o = i - 524288L;  dst = cfg::B_WIN;          NcS = 1024; Kd = 512; }
    else if (i < 1572864L) { W = Wfi; o = i - 1048576L; dst = cfg::B_WIN + 524288; NcS = 1024; Kd = 512; }
    else if (i < 2621440L) { W = Weh; o = i - 1572864L; dst = cfg::B_WEH;          NcS = 1024; Kd = 1024; }
    else                   { W = Wfh; o = i - 2621440L; dst = cfg::B_WFH;          NcS = 1024; Kd = 1024; }
    int n = (int)(o / Kd);
    int k = (int)(o % Kd);
    g_hf[dst + o] = __float2half(W[(long)k * NcS + n]);
}

// biases + csr counter zeroing merged
__global__ void setup_kernel(const float* __restrict__ bq, const float* __restrict__ bk,
                             const float* __restrict__ bei, const float* __restrict__ bfi,
                             const float* __restrict__ beh, const float* __restrict__ bfh)
{
    int i = blockIdx.x * blockDim.x + threadIdx.x;
    if (i < 1024) g_f[cfg::OFF_BQK + i] = (i < 512) ? bq[i] : bk[i - 512];
    else if (i < 3072) { int j = i - 1024; g_f[cfg::OFF_BIN + j] = (j < 1024) ? bei[j] : bfi[j - 1024]; }
    else if (i < 4096) g_f[cfg::OFF_BEH + i - 3072] = beh[i - 3072];
    else if (i < 5120) g_f[cfg::OFF_BFH + i - 4096] = bfh[i - 4096];
    int z = i - 5120;
    if (z >= 0 && z <= cfg::N) g_i[cfg::I_WOFS + z] = 0;
}

// ===========================================================================
// CSR build
// ===========================================================================
__global__ void csr_count(const int* __restrict__ ei) {
    int e = blockIdx.x * blockDim.x + threadIdx.x;
    if (e < cfg::E) atomicAdd(&g_i[cfg::I_WOFS + ei[e]], 1);
}
__global__ __launch_bounds__(1024) void csr_scan() {
    __shared__ int sh[1024];
    int t = threadIdx.x;
    int loc[20];
    int base = t * 20;
    int sum = 0;
#pragma unroll
    for (int j = 0; j < 20; j++) {
        int idx = base + j;
        int v = (idx < cfg::N) ? g_i[cfg::I_WOFS + idx] : 0;
        loc[j] = sum;
        sum += v;
    }
    sh[t] = sum;
    __syncthreads();
    for (int off = 1; off < 1024; off <<= 1) {
        int v = (t >= off) ? sh[t - off] : 0;
        __syncthreads();
        sh[t] += v;
        __syncthreads();
    }
    int pre = (t == 0) ? 0 : sh[t - 1];
#pragma unroll
    for (int j = 0; j < 20; j++) {
        int idx = base + j;
        if (idx < cfg::N) {
            g_i[cfg::I_ROWPTR + idx] = pre + loc[j];
            g_i[cfg::I_WOFS + idx]   = pre + loc[j];
        }
    }
    if (t == 0) g_i[cfg::I_ROWPTR + cfg::N] = cfg::E;
}
__global__ void csr_scatter(const int* __restrict__ ei, const float* __restrict__ att_bias) {
    int e = blockIdx.x * blockDim.x + threadIdx.x;
    if (e >= cfg::E) return;
    int r = ei[e];
    int p = atomicAdd(&g_i[cfg::I_WOFS + r], 1);
    g_i[cfg::I_COL + p] = ei[cfg::E + e];
    g_f[cfg::OFF_CB + p] = att_bias[e];
}

// ===========================================================================
// one-pass edge attention (fp16 q/k): warp per node, online softmax,
// 2-way ILP + metadata prefetch
// ===========================================================================
__global__ __launch_bounds__(256) void edge_attn_kernel(const float* __restrict__ pos) {
    int n = blockIdx.x * 8 + (threadIdx.x >> 5);
    if (n >= cfg::N) return;
    int lane = threadIdx.x & 31;

    int base = g_i[cfg::I_ROWPTR + n];
    int deg  = g_i[cfg::I_ROWPTR + n + 1] - base;

    const float4* qr = reinterpret_cast<const float4*>(g_hf + cfg::B_QKA + (long)n * 1024) + lane * 2;
    float q[16];
    h8_to_f(qr[0], q);
    h8_to_f(qr[1], q + 8);

    float prv = (lane < 3) ? pos[(long)n * 3 + lane] : 0.f;
    float prx = __shfl_sync(0xffffffffu, prv, 0);
    float pry = __shfl_sync(0xffffffffu, prv, 1);
    float prz = __shfl_sync(0xffffffffu, prv, 2);

    float m = -1e30f, d = 0.f, a0 = 0.f, a1 = 0.f, a2 = 0.f;

    int i = 0;
    // prefetched metadata for the current pair
    int c0 = 0, c1 = 0;
    float b0 = 0.f, b1 = 0.f;
    if (i + 2 <= deg) {
        c0 = g_i[cfg::I_COL + base];
        c1 = g_i[cfg::I_COL + base + 1];
        b0 = g_f[cfg::OFF_CB + base];
        b1 = g_f[cfg::OFF_CB + base + 1];
    }
    for (; i + 2 <= deg; i += 2) {
        const float4* kr0 = reinterpret_cast<const float4*>(g_hf + cfg::B_QKA + (long)c0 * 1024 + 512) + lane * 2;
        const float4* kr1 = reinterpret_cast<const float4*>(g_hf + cfg::B_QKA + (long)c1 * 1024 + 512) + lane * 2;
        float4 v00 = kr0[0], v01 = kr0[1];
        float4 v10 = kr1[0], v11 = kr1[1];
        float pv0 = (lane < 3) ? pos[(long)c0 * 3 + lane] : 0.f;
        float pv1 = (lane < 3) ? pos[(long)c1 * 3 + lane] : 0.f;
        float lb0 = b0, lb1 = b1;
        // prefetch next pair's metadata while dots compute
        if (i + 4 <= deg) {
            c0 = g_i[cfg::I_COL + base + i + 2];
            c1 = g_i[cfg::I_COL + base + i + 3];
            b0 = g_f[cfg::OFF_CB + base + i + 2];
            b1 = g_f[cfg::OFF_CB + base + i + 3];
        }
        float kv[16];
        float s0 = 0.f, s1 = 0.f;
        h8_to_f(v00, kv); h8_to_f(v01, kv + 8);
#pragma unroll
        for (int j = 0; j < 16; j++) s0 = fmaf(q[j], kv[j], s0);
        h8_to_f(v10, kv); h8_to_f(v11, kv + 8);
#pragma unroll
        for (int j = 0; j < 16; j++) s1 = fmaf(q[j], kv[j], s1);
        s0 += __shfl_xor_sync(0xffffffffu, s0, 1);
        s1 += __shfl_xor_sync(0xffffffffu, s1, 1);
        s0 += __shfl_xor_sync(0xffffffffu, s0, 2);
        s1 += __shfl_xor_sync(0xffffffffu, s1, 2);

        float p0x = __shfl_sync(0xffffffffu, pv0, 0);
        float p0y = __shfl_sync(0xffffffffu, pv0, 1);
        float p0z = __shfl_sync(0xffffffffu, pv0, 2);
        float p1x = __shfl_sync(0xffffffffu, pv1, 0);
        float p1y = __shfl_sync(0xffffffffu, pv1, 1);
        float p1z = __shfl_sync(0xffffffffu, pv1, 2);

        float lg0 = s0 * 0.125f + lb0;
        float lg1 = s1 * 0.125f + lb1;
        float nm = fmaxf(m, fmaxf(lg0, lg1));
        float sc = expf(m - nm);
        float p0 = expf(lg0 - nm);
        float p1 = expf(lg1 - nm);
        d  = d  * sc + p0 + p1;
        a0 = a0 * sc + p0 * p0x + p1 * p1x;
        a1 = a1 * sc + p0 * p0y + p1 * p1y;
        a2 = a2 * sc + p0 * p0z + p1 * p1z;
        m = nm;
    }
    for (; i < deg; i++) {
        int c = g_i[cfg::I_COL + base + i];
        float bias = g_f[cfg::OFF_CB + base + i];
        const float4* kr = reinterpret_cast<const float4*>(g_hf + cfg::B_QKA + (long)c * 1024 + 512) + lane * 2;
        float kv[16];
        h8_to_f(kr[0], kv);
        h8_to_f(kr[1], kv + 8);
        float s = 0.f;
#pragma unroll
        for (int j = 0; j < 16; j++) s = fmaf(q[j], kv[j], s);
        s += __shfl_xor_sync(0xffffffffu, s, 1);
        s += __shfl_xor_sync(0xffffffffu, s, 2);

        float pv = (lane < 3) ? pos[(long)c * 3 + lane] : 0.f;
        float px = __shfl_sync(0xffffffffu, pv, 0);
        float py = __shfl_sync(0xffffffffu, pv, 1);
        float pz = __shfl_sync(0xffffffffu, pv, 2);

        float lg = s * 0.125f + bias;
        float nm = fmaxf(m, lg);
        float sc = expf(m - nm);
        float p  = expf(lg - nm);
        d  = d  * sc + p;
        a0 = a0 * sc + p * px;
        a1 = a1 * sc + p * py;
        a2 = a2 * sc + p * pz;
        m = nm;
    }

    if ((lane & 3) == 0) {
        int h = lane >> 2;
        float inv = (d > 0.f) ? 1.0f / d : 0.f;
        long o = (long)n * 24 + h * 3;
        g_f[cfg::OFF_ATT + o + 0] = a0 * inv - prx;
        g_f[cfg::OFF_ATT + o + 1] = a1 * inv - pry;
        g_f[cfg::OFF_ATT + o + 2] = a2 * inv - prz;
    }
}

// ===========================================================================
// forces h1 fixup: h1f = gelu(raw(fp16) + attminus @ W24) -> fp16 (2-row ILP)
// ===========================================================================
constexpr int FIX_SMEM = (24 * 1025 + 16 * 24) * 4;

__global__ __launch_bounds__(256) void forces_h1_kernel(const float* __restrict__ Wfi) {
    extern __shared__ float sw[];
    float* w24 = sw;
    float* am  = sw + 24 * 1025;
    int n0 = blockIdx.x * 16;
    int t = threadIdx.x;

    for (int idx = t; idx < 24 * 1024; idx += 256) {
        int k = idx >> 10, j = idx & 1023;
        w24[k * 1025 + j] = Wfi[(long)(512 + k) * 1024 + j];
    }
    for (int idx = t; idx < 16 * 24; idx += 256) {
        int i = idx / 24, k = idx % 24;
        am[idx] = g_f[cfg::OFF_ATT + (long)(n0 + i) * 24 + k];
    }
    __syncthreads();

#pragma unroll
    for (int jj = 0; jj < 4; jj++) {
        int j = t + jj * 256;
        float w[24];
#pragma unroll
        for (int k = 0; k < 24; k++) w[k] = w24[k * 1025 + j];
#pragma unroll 2
        for (int i = 0; i < 16; i += 2) {
            long gi0 = (long)(n0 + i) * 1024 + j;
            long gi1 = (long)(n0 + i + 1) * 1024 + j;
            float v0 = __half2float(g_hf[cfg::B_RAWF + gi0]);
            float v1 = __half2float(g_hf[cfg::B_RAWF + gi1]);
#pragma unroll
            for (int k = 0; k < 24; k++) {
                v0 = fmaf(am[i * 24 + k], w[k], v0);
                v1 = fmaf(am[(i + 1) * 24 + k], w[k], v1);
            }
            g_hf[cfg::B_H1F + gi0] = __float2half(gelu_tanh(v0));
            g_hf[cfg::B_H1F + gi1] = __float2half(gelu_tanh(v1));
        }
    }
}

// ===========================================================================
// double LayerNorm -> fp16 activations
// ===========================================================================
__global__ __launch_bounds__(128) void ln_kernel(
    const float* __restrict__ x,
    const float* __restrict__ ga, const float* __restrict__ ba,
    const float* __restrict__ gm, const float* __restrict__ bm)
{
    int row = blockIdx.x;
    int t = threadIdx.x;
    const float* xr = x + (long)row * cfg::D;

    float v[4];
    float s = 0.f, ss = 0.f;
#pragma unroll
    for (int i = 0; i < 4; i++) {
        v[i] = xr[t + 128 * i];
        s += v[i];
        ss += v[i] * v[i];
    }
    __shared__ float sh[2][4];
#pragma unroll
    for (int o = 16; o > 0; o >>= 1) {
        s  += __shfl_down_sync(0xffffffffu, s, o);
        ss += __shfl_down_sync(0xffffffffu, ss, o);
    }
    if ((t & 31) == 0) { sh[0][t >> 5] = s; sh[1][t >> 5] = ss; }
    __syncthreads();
    if (t == 0) {
        float S  = sh[0][0] + sh[0][1] + sh[0][2] + sh[0][3];
        float SS = sh[1][0] + sh[1][1] + sh[1][2] + sh[1][3];
        float mean = S / cfg::D;
        float var  = SS / cfg::D - mean * mean;
        sh[0][0] = mean;
        sh[1][0] = rsqrtf(var + 1e-5f);
    }
    __syncthreads();
    float mean = sh[0][0], rstd = sh[1][0];
#pragma unroll
    for (int i = 0; i < 4; i++) {
        int c = t + 128 * i;
        float zn = (v[i] - mean) * rstd;
        g_hf[cfg::B_ZATT + (long)row * cfg::D + c] = __float2half(zn * ga[c] + ba[c]);
        g_hf[cfg::B_ZMLP + (long)row * cfg::D + c] = __float2half(zn * gm[c] + bm[c]);
    }
}

// ===========================================================================
// fused output heads (h2 fp16), 2 nodes per block (128 threads each)
// ===========================================================================
__global__ __launch_bounds__(256) void heads_kernel(
    const float* __restrict__ Weo, const float* __restrict__ beo,
    const float* __restrict__ Wfo, const float* __restrict__ bfo,
    float* __restrict__ out)
{
    int sub = threadIdx.x >> 7;           // 0 or 1
    int n = blockIdx.x * 2 + sub;
    int t = threadIdx.x & 127;
    const __half2* he = reinterpret_cast<const __half2*>(g_hf + cfg::B_H2E + (long)n * 1024);
    const __half2* hf = reinterpret_cast<const __half2*>(g_hf + cfg::B_H2F + (long)n * 1024);
    float s = 0.f, s0 = 0.f, s1 = 0.f, s2 = 0.f;
#pragma unroll
    for (int jj = 0; jj < 4; jj++) {
        int j = t + jj * 128;
        float2 e2 = __half22float2(he[j]);
        float2 f2 = __half22float2(hf[j]);
        int j0 = 2 * j, j1 = 2 * j + 1;
        s += e2.x * Weo[j0] + e2.y * Weo[j1];
        s0 += f2.x * Wfo[j0 * 3 + 0] + f2.y * Wfo[j1 * 3 + 0];
        s1 += f2.x * Wfo[j0 * 3 + 1] + f2.y * Wfo[j1 * 3 + 1];
        s2 += f2.x * Wfo[j0 * 3 + 2] + f2.y * Wfo[j1 * 3 + 2];
    }
    __shared__ float sh[2][4][4];
#pragma unroll
    for (int o = 16; o > 0; o >>= 1) {
        s  += __shfl_down_sync(0xffffffffu, s,  o);
        s0 += __shfl_down_sync(0xffffffffu, s0, o);
        s1 += __shfl_down_sync(0xffffffffu, s1, o);
        s2 += __shfl_down_sync(0xffffffffu, s2, o);
    }
    if ((t & 31) == 0) {
        int w = t >> 5;   // 0..3
        sh[sub][0][w] = s; sh[sub][1][w] = s0; sh[sub][2][w] = s1; sh[sub][3][w] = s2;
    }
    __syncthreads();
    if (t == 0) {
        float t0 = 0.f, t1 = 0.f, t2 = 0.f, t3 = 0.f;
#pragma unroll
        for (int i = 0; i < 4; i++) { t0 += sh[sub][0][i]; t1 += sh[sub][1][i]; t2 += sh[sub][2][i]; t3 += sh[sub][3][i]; }
        out[n] = t0 + beo[0];
        out[(long)cfg::N + (long)n * 3 + 0] = t1 + bfo[0];
        out[(long)cfg::N + (long)n * 3 + 1] = t2 + bfo[1];
        out[(long)cfg::N + (long)n * 3 + 2] = t3 + bfo[2];
    }
}

// ===========================================================================
extern "C" void kernel_launch(void* const* d_in, const int* in_sizes, int n_in,
                              void* d_out, int out_size)
{
    const float* x        = (const float*)d_in[0];
    const int*   ei       = (const int*)  d_in[1];
    const float* att_bias = (const float*)d_in[2];
    const float* pos      = (const float*)d_in[3];
    const float* g_att  = (const float*)d_in[5];
    const float* b_att  = (const float*)d_in[6];
    const float* g_mlp  = (const float*)d_in[7];
    const float* b_mlp  = (const float*)d_in[8];
    const float* Wq     = (const float*)d_in[9];
    const float* bq     = (const float*)d_in[10];
    const float* Wk     = (const float*)d_in[11];
    const float* bk     = (const float*)d_in[12];
    const float* We_in  = (const float*)d_in[13];
    const float* be_in  = (const float*)d_in[14];
    const float* We_h   = (const float*)d_in[15];
    const float* be_h   = (const float*)d_in[16];
    const float* We_out = (const float*)d_in[17];
    const float* be_out = (const float*)d_in[18];
    const float* Wf_in  = (const float*)d_in[19];
    const float* bf_in  = (const float*)d_in[20];
    const float* Wf_h   = (const float*)d_in[21];
    const float* bf_h   = (const float*)d_in[22];
    const float* Wf_out = (const float*)d_in[23];
    const float* bf_out = (const float*)d_in[24];
    float* out = (float*)d_out;

    cudaFuncSetAttribute(gemm_proj,   cudaFuncAttributeMaxDynamicSharedMemorySize, GEMM_SMEM);
    cudaFuncSetAttribute(gemm_hidden, cudaFuncAttributeMaxDynamicSharedMemorySize, GEMM_SMEM);
    cudaFuncSetAttribute(forces_h1_kernel, cudaFuncAttributeMaxDynamicSharedMemorySize, FIX_SMEM);

    const int MB = (cfg::N + 127) / 128;   // 157

    // 0: biases + zero csr counters
    setup_kernel<<<(5120 + cfg::N + 1 + 255) / 256, 256>>>(bq, bk, be_in, bf_in, be_h, bf_h);
    // 1: LayerNorm
    ln_kernel<<<cfg::N, 128>>>(x, g_att, b_att, g_mlp, b_mlp);
    // 2: weights
    conv_all<<<(unsigned)((3670016L + 255) / 256), 256>>>(Wq, Wk, We_in, Wf_in, We_h, Wf_h);
    // 3: csr count
    csr_count<<<(cfg::E + 255) / 256, 256>>>(ei);
    // 4: merged QK + in-projection (x<8: QK, x>=8: IN)
    gemm_proj<<<dim3(24, MB), 256, GEMM_SMEM>>>(cfg::N);
    // 5: csr scan
    csr_scan<<<1, 1024>>>();
    // 6: csr scatter
    csr_scatter<<<(cfg::E + 255) / 256, 256>>>(ei, att_bias);
    // 7: one-pass edge attention (2-way ILP + metadata prefetch)
    edge_attn_kernel<<<(cfg::N + 7) / 8, 256>>>(pos);
    // 8: forces h1 fixup
    forces_h1_kernel<<<cfg::N / 16, 256, FIX_SMEM>>>(Wf_in);
    // 9: merged hidden blocks (z: 0=energy, 1=forces), h2 -> fp16
    gemm_hidden<<<dim3(8, MB, 2), 256, GEMM_SMEM>>>(
        cfg::B_H1E, cfg::B_H1F, cfg::B_WEH, cfg::B_WFH,
        cfg::OFF_BEH, cfg::OFF_BFH, cfg::B_H2E, cfg::B_H2F, cfg::N);
    // 10: output heads (2 nodes/block)
    heads_kernel<<<cfg::N / 2, 256>>>(We_out, be_out, Wf_out, bf_out, out);
}